// round 8
// baseline (speedup 1.0000x reference)
#include <cuda_runtime.h>
#include <cuda_bf16.h>

// Problem constants
#define NN 50000
#define EE 800000

// ---------------- scratch (device globals; no allocation allowed) -----------
// Kernels resolve these via buf(id) in device code; no host symbol APIs.
__device__ float g_h  [(long long)NN * 128];
__device__ float g_s  [(long long)NN * 128];
__device__ float g_agg[(long long)NN * 128];
__device__ float g_m  [(long long)NN * 256];
__device__ float g_gi [(long long)NN * 384];
__device__ float g_gh [(long long)NN * 384];
__device__ float g_inv[NN];
__device__ int   g_cnt[NN];

#define BUF_H   0
#define BUF_S   1
#define BUF_AGG 2
#define BUF_M   3
#define BUF_GI  4
#define BUF_GH  5

__device__ __forceinline__ float* buf(int id) {
    switch (id) {
        case BUF_H:   return g_h;
        case BUF_S:   return g_s;
        case BUF_AGG: return g_agg;
        case BUF_M:   return g_m;
        case BUF_GI:  return g_gi;
        case BUF_GH:  return g_gh;
    }
    return nullptr;
}

// ---------------- small utility kernels -------------------------------------
__global__ void zero_agg_kernel() {
    long long i = (long long)blockIdx.x * blockDim.x + threadIdx.x;
    long long n4 = (long long)NN * 128 / 4;
    if (i < n4) ((float4*)g_agg)[i] = make_float4(0.f, 0.f, 0.f, 0.f);
}

__global__ void zero_cnt_kernel() {
    int i = blockIdx.x * blockDim.x + threadIdx.x;
    if (i < NN) g_cnt[i] = 0;
}

// edge_index is int32 (JAX x64 disabled: jnp.int64 degrades to int32)
__global__ void count_kernel(const int* __restrict__ ei) {
    int e = blockIdx.x * blockDim.x + threadIdx.x;
    if (e < EE) {
        unsigned c = (unsigned)ei[EE + e];
        if (c < NN) atomicAdd(&g_cnt[c], 1);
    }
}

__global__ void inv_kernel() {
    int n = blockIdx.x * blockDim.x + threadIdx.x;
    if (n < NN) {
        int c = g_cnt[n];
        g_inv[n] = 1.0f / (float)(c > 0 ? c : 1);
    }
}

// ---------------- edge scatter: agg[col] += s[row] * ea ---------------------
// One warp per edge; lane handles one float4 (32 lanes * 4 = 128 floats).
__global__ void scatter_kernel(const int* __restrict__ ei,
                               const float* __restrict__ ea) {
    long long gid = (long long)blockIdx.x * blockDim.x + threadIdx.x;
    int e = (int)(gid >> 5);
    int lane = (int)(gid & 31);
    if (e >= EE) return;
    unsigned r = (unsigned)ei[e];
    unsigned c = (unsigned)ei[EE + e];
    if (r >= NN || c >= NN) return;
    float a = ea[e];
    float4 v = ((const float4*)(g_s + (long long)r * 128))[lane];
    float* ag = g_agg + (long long)c * 128 + lane * 4;
    atomicAdd(ag + 0, v.x * a);
    atomicAdd(ag + 1, v.y * a);
    atomicAdd(ag + 2, v.z * a);
    atomicAdd(ag + 3, v.w * a);
}

// ---------------- generic SGEMM --------------------------------------------
// C[M x Nc] = act( concat(A0*inv?, A1)[M x (K0+K1)] @ W[(K0+K1) x Nc] + bias )
// BM=BN=128, BK=16, 256 threads, 8x8 micro-tile per thread.
// K0 and K1 are multiples of 16; Nc is a multiple of 128. Only M has a tail.
// act: 0 = identity, 1 = leaky_relu(0.01)
__global__ __launch_bounds__(256)
void gemm_kernel(const float* __restrict__ A0p, int A0id, int K0, int useInvScale,
                 int A1id, int K1,
                 const float* __restrict__ W,
                 const float* __restrict__ bias,
                 float* __restrict__ Cp, int Cid,
                 int M, int Nc, int act) {
    const int BM = 128, BK = 16;
    __shared__ float As[BK][132];   // padded: 132 keeps float4 alignment
    __shared__ float Bs[BK][132];

    const float* A0 = (A0id >= 0) ? buf(A0id) : A0p;
    const float* A1 = (A1id >= 0) ? buf(A1id) : nullptr;
    float*       C  = (Cid  >= 0) ? buf(Cid)  : Cp;

    const int K = K0 + K1;
    const int m0 = blockIdx.x * BM;
    const int n0 = blockIdx.y * 128;
    const int t  = threadIdx.x;
    const int ty = t >> 4;          // 0..15  (row group)
    const int tx = t & 15;          // 0..15  (col group)

    float acc[8][8];
#pragma unroll
    for (int i = 0; i < 8; i++)
#pragma unroll
        for (int j = 0; j < 8; j++) acc[i][j] = 0.f;

    for (int k0 = 0; k0 < K; k0 += BK) {
        // --- load A tile (transposed into As[k][m]) : 512 float4s, 2/thread
#pragma unroll
        for (int q = 0; q < 2; q++) {
            int idx = t + q * 256;          // [0,512)
            int row = idx >> 2;             // 0..127
            int kc  = (idx & 3) * 4;        // 0,4,8,12
            int grow = m0 + row;
            float4 v = make_float4(0.f, 0.f, 0.f, 0.f);
            if (grow < M) {
                int kg = k0 + kc;
                if (kg < K0) {
                    v = *(const float4*)(A0 + (long long)grow * K0 + kg);
                    if (useInvScale) {
                        float sc = g_inv[grow];
                        v.x *= sc; v.y *= sc; v.z *= sc; v.w *= sc;
                    }
                } else {
                    v = *(const float4*)(A1 + (long long)grow * K1 + (kg - K0));
                }
            }
            As[kc + 0][row] = v.x;
            As[kc + 1][row] = v.y;
            As[kc + 2][row] = v.z;
            As[kc + 3][row] = v.w;
        }
        // --- load W tile: Bs[k][n], 512 float4s, 2/thread, fully coalesced
#pragma unroll
        for (int q = 0; q < 2; q++) {
            int idx = t + q * 256;          // [0,512)
            int kr  = idx >> 5;             // 0..15
            int nc  = (idx & 31) * 4;       // 0..124
            float4 v = *(const float4*)(W + (long long)(k0 + kr) * Nc + n0 + nc);
            *(float4*)&Bs[kr][nc] = v;
        }
        __syncthreads();

#pragma unroll
        for (int kk = 0; kk < BK; kk++) {
            float a[8], b[8];
#pragma unroll
            for (int i = 0; i < 8; i++) a[i] = As[kk][ty * 8 + i];
#pragma unroll
            for (int j = 0; j < 8; j++) b[j] = Bs[kk][tx * 8 + j];
#pragma unroll
            for (int i = 0; i < 8; i++)
#pragma unroll
                for (int j = 0; j < 8; j++) acc[i][j] += a[i] * b[j];
        }
        __syncthreads();
    }

    // --- epilogue: bias + activation + store (float4)
#pragma unroll
    for (int i = 0; i < 8; i++) {
        int grow = m0 + ty * 8 + i;
        if (grow >= M) continue;
#pragma unroll
        for (int j = 0; j < 8; j += 4) {
            int gc = n0 + tx * 8 + j;
            float4 v;
            v.x = acc[i][j + 0] + bias[gc + 0];
            v.y = acc[i][j + 1] + bias[gc + 1];
            v.z = acc[i][j + 2] + bias[gc + 2];
            v.w = acc[i][j + 3] + bias[gc + 3];
            if (act == 1) {
                v.x = v.x > 0.f ? v.x : 0.01f * v.x;
                v.y = v.y > 0.f ? v.y : 0.01f * v.y;
                v.z = v.z > 0.f ? v.z : 0.01f * v.z;
                v.w = v.w > 0.f ? v.w : 0.01f * v.w;
            }
            *(float4*)(C + (long long)grow * Nc + gc) = v;
        }
    }
}

// ---------------- GRU elementwise update ------------------------------------
// Reads g_gi, g_gh, g_h; writes d_out if writeOut else g_h.
__global__ void gru_kernel(float* __restrict__ doutp, int writeOut) {
    long long idx = (long long)blockIdx.x * blockDim.x + threadIdx.x;
    if (idx >= (long long)NN * 128) return;
    int n = (int)(idx >> 7);
    int j = (int)(idx & 127);
    const float* gin = g_gi + (long long)n * 384;
    const float* ghn = g_gh + (long long)n * 384;
    float ir  = gin[j],       hr = ghn[j];
    float iz  = gin[128 + j], hz = ghn[128 + j];
    float inn = gin[256 + j], hn = ghn[256 + j];
    float r = 1.f / (1.f + __expf(-(ir + hr)));
    float z = 1.f / (1.f + __expf(-(iz + hz)));
    float nv = tanhf(inn + r * hn);
    float res = (1.f - z) * nv + z * g_h[idx];
    if (writeOut) doutp[idx] = res;
    else          g_h[idx] = res;
}

// ---------------- launch -----------------------------------------------------
extern "C" void kernel_launch(void* const* d_in, const int* in_sizes, int n_in,
                              void* d_out, int out_size) {
    const float* x  = (const float*)d_in[0];
    const int*   ei = (const int*)d_in[1];     // int32! (JAX x64 disabled)
    const float* ea = (const float*)d_in[2];
    // d_in[3] = batch (int32, unused)
    const float* W_embed = (const float*)d_in[4];
    const float* b_embed = (const float*)d_in[5];
    const float* W_snd   = (const float*)d_in[6];
    const float* b_snd   = (const float*)d_in[7];
    const float* W_rec   = (const float*)d_in[8];
    const float* b_rec   = (const float*)d_in[9];
    const float* W_ih    = (const float*)d_in[10];
    const float* b_ih    = (const float*)d_in[11];
    const float* W_hh    = (const float*)d_in[12];
    const float* b_hh    = (const float*)d_in[13];

    const int T = 256;
    const int rowBlocks = (NN + 127) / 128;   // 391

    // degree counts (deterministic per call)
    zero_cnt_kernel<<<(NN + T - 1) / T, T>>>();
    count_kernel<<<(EE + T - 1) / T, T>>>(ei);
    inv_kernel<<<(NN + T - 1) / T, T>>>();

    // embed: h = x @ W_embed + b_embed
    gemm_kernel<<<dim3(rowBlocks, 1), T>>>(x, -1, 64, 0, -1, 0,
                                           W_embed, b_embed,
                                           nullptr, BUF_H, NN, 128, 0);

    for (int layer = 0; layer < 3; layer++) {
        // s = leaky_relu(h @ W_snd + b_snd)
        gemm_kernel<<<dim3(rowBlocks, 1), T>>>(nullptr, BUF_H, 128, 0, -1, 0,
                                               W_snd, b_snd,
                                               nullptr, BUF_S, NN, 128, 1);
        // agg = segment_sum(s[row] * ea, col)
        long long n4 = (long long)NN * 128 / 4;
        zero_agg_kernel<<<(unsigned)((n4 + T - 1) / T), T>>>();
        long long sthreads = (long long)EE * 32;
        scatter_kernel<<<(unsigned)((sthreads + T - 1) / T), T>>>(ei, ea);
        // m = leaky_relu([agg * inv, h] @ W_rec + b_rec)
        gemm_kernel<<<dim3(rowBlocks, 2), T>>>(nullptr, BUF_AGG, 128, 1, BUF_H, 128,
                                               W_rec, b_rec,
                                               nullptr, BUF_M, NN, 256, 1);
        // gi = m @ W_ih + b_ih ; gh = h @ W_hh + b_hh
        gemm_kernel<<<dim3(rowBlocks, 3), T>>>(nullptr, BUF_M, 256, 0, -1, 0,
                                               W_ih, b_ih,
                                               nullptr, BUF_GI, NN, 384, 0);
        gemm_kernel<<<dim3(rowBlocks, 3), T>>>(nullptr, BUF_H, 128, 0, -1, 0,
                                               W_hh, b_hh,
                                               nullptr, BUF_GH, NN, 384, 0);
        // GRU update (last layer writes d_out)
        long long gthreads = (long long)NN * 128;
        gru_kernel<<<(unsigned)((gthreads + T - 1) / T), T>>>(
            (float*)d_out, layer == 2 ? 1 : 0);
    }
}

// round 9
// speedup vs baseline: 1.3771x; 1.3771x over previous
#include <cuda_runtime.h>
#include <cuda_bf16.h>

// Problem constants
#define NN 50000
#define EE 800000

// ---------------- scratch (device globals; no allocation allowed) -----------
__device__ float g_h  [(long long)NN * 128];
__device__ float g_s  [(long long)NN * 128];
__device__ float g_agg[(long long)NN * 128];
__device__ float g_m  [(long long)NN * 256];
__device__ float g_gi [(long long)NN * 384];
__device__ float g_gh [(long long)NN * 384];
__device__ float g_inv[NN];
__device__ int   g_cnt[NN];
__device__ int   g_start[NN + 1];
__device__ int   g_head[NN];
__device__ int   g_csr_row[EE];
__device__ float g_csr_ea[EE];

#define BUF_H   0
#define BUF_S   1
#define BUF_AGG 2
#define BUF_M   3
#define BUF_GI  4
#define BUF_GH  5

__device__ __forceinline__ float* buf(int id) {
    switch (id) {
        case BUF_H:   return g_h;
        case BUF_S:   return g_s;
        case BUF_AGG: return g_agg;
        case BUF_M:   return g_m;
        case BUF_GI:  return g_gi;
        case BUF_GH:  return g_gh;
    }
    return nullptr;
}

// ---------------- degree / CSR build ----------------------------------------
__global__ void zero_cnt_kernel() {
    int i = blockIdx.x * blockDim.x + threadIdx.x;
    if (i < NN) g_cnt[i] = 0;
}

// edge_index is int32 (JAX x64 disabled)
__global__ void count_kernel(const int* __restrict__ ei) {
    int e = blockIdx.x * blockDim.x + threadIdx.x;
    if (e < EE) {
        unsigned c = (unsigned)ei[EE + e];
        if (c < NN) atomicAdd(&g_cnt[c], 1);
    }
}

// Single-block exclusive scan over g_cnt -> g_start, g_head, g_inv.
__global__ void scan_kernel() {
    __shared__ int ssum[1024];
    const int CH = (NN + 1023) / 1024;   // 49
    int t = threadIdx.x;
    int beg = t * CH;
    int end = beg + CH; if (end > NN) end = NN;
    int s = 0;
    for (int i = beg; i < end; i++) s += g_cnt[i];
    ssum[t] = s;
    __syncthreads();
    for (int off = 1; off < 1024; off <<= 1) {
        int v = (t >= off) ? ssum[t - off] : 0;
        __syncthreads();
        ssum[t] += v;
        __syncthreads();
    }
    int run = ssum[t] - s;   // exclusive prefix for this chunk
    for (int i = beg; i < end; i++) {
        int c = g_cnt[i];
        g_start[i] = run;
        g_head[i]  = run;
        g_inv[i]   = 1.0f / (float)(c > 0 ? c : 1);
        run += c;
    }
    if (t == 1023) g_start[NN] = ssum[1023];
}

__global__ void fill_kernel(const int* __restrict__ ei,
                            const float* __restrict__ ea) {
    int e = blockIdx.x * blockDim.x + threadIdx.x;
    if (e >= EE) return;
    unsigned r = (unsigned)ei[e];
    unsigned c = (unsigned)ei[EE + e];
    if (c < NN) {
        int p = atomicAdd(&g_head[c], 1);
        g_csr_row[p] = (r < NN) ? (int)r : 0;
        g_csr_ea[p]  = ea[e];
    }
}

// ---------------- node-parallel aggregation (no atomics) --------------------
// One warp per node: agg[n] = (sum_{e in in(n)} s[row[e]] * ea[e]) * inv[n]
__global__ void agg_kernel() {
    int gid  = blockIdx.x * blockDim.x + threadIdx.x;
    int n    = gid >> 5;
    int lane = gid & 31;
    if (n >= NN) return;
    int beg = g_start[n];
    int end = g_start[n + 1];
    float4 acc = make_float4(0.f, 0.f, 0.f, 0.f);
    int e = beg;
    for (; e + 1 < end; e += 2) {
        int   r0 = g_csr_row[e];
        int   r1 = g_csr_row[e + 1];
        float a0 = g_csr_ea[e];
        float a1 = g_csr_ea[e + 1];
        float4 v0 = ((const float4*)(g_s + (long long)r0 * 128))[lane];
        float4 v1 = ((const float4*)(g_s + (long long)r1 * 128))[lane];
        acc.x += v0.x * a0 + v1.x * a1;
        acc.y += v0.y * a0 + v1.y * a1;
        acc.z += v0.z * a0 + v1.z * a1;
        acc.w += v0.w * a0 + v1.w * a1;
    }
    if (e < end) {
        int   r0 = g_csr_row[e];
        float a0 = g_csr_ea[e];
        float4 v0 = ((const float4*)(g_s + (long long)r0 * 128))[lane];
        acc.x += v0.x * a0; acc.y += v0.y * a0;
        acc.z += v0.z * a0; acc.w += v0.w * a0;
    }
    float iv = g_inv[n];
    acc.x *= iv; acc.y *= iv; acc.z *= iv; acc.w *= iv;
    ((float4*)(g_agg + (long long)n * 128))[lane] = acc;
}

// ---------------- SGEMM: double-buffered, packed f32x2 inner loop -----------
// C[M x Nc] = act( concat(A0, A1)[M x (K0+K1)] @ W[(K0+K1) x Nc] + bias )
// BM=BN=128, BK=16, 256 threads, 8x8 micro-tile per thread.
__global__ __launch_bounds__(256)
void gemm_kernel(const float* __restrict__ A0p, int A0id, int K0,
                 int A1id, int K1,
                 const float* __restrict__ W,
                 const float* __restrict__ bias,
                 float* __restrict__ Cp, int Cid,
                 int M, int Nc, int act) {
    const int BK = 16;
    __shared__ float As[2][BK][132];
    __shared__ float Bs[2][BK][132];

    const float* A0 = (A0id >= 0) ? buf(A0id) : A0p;
    const float* A1 = (A1id >= 0) ? buf(A1id) : nullptr;
    float*       C  = (Cid  >= 0) ? buf(Cid)  : Cp;

    const int K  = K0 + K1;
    const int m0 = blockIdx.x * 128;
    const int n0 = blockIdx.y * 128;
    const int t  = threadIdx.x;
    const int ty = t >> 4;          // 0..15
    const int tx = t & 15;          // 0..15

    // packed accumulators: acc[i][jp] holds (c[i][2jp], c[i][2jp+1])
    unsigned long long acc[8][4];
#pragma unroll
    for (int i = 0; i < 8; i++)
#pragma unroll
        for (int jp = 0; jp < 4; jp++) acc[i][jp] = 0ULL;

    float4 pa[2], pb[2];

    auto load_tiles = [&](int k0) {
#pragma unroll
        for (int q = 0; q < 2; q++) {
            int idx = t + q * 256;          // [0,512)
            int row = idx >> 2;             // 0..127
            int kc  = (idx & 3) * 4;        // 0,4,8,12
            int grow = m0 + row;
            float4 v = make_float4(0.f, 0.f, 0.f, 0.f);
            if (grow < M) {
                int kg = k0 + kc;
                if (kg < K0) v = *(const float4*)(A0 + (long long)grow * K0 + kg);
                else         v = *(const float4*)(A1 + (long long)grow * K1 + (kg - K0));
            }
            pa[q] = v;
            int kr = idx >> 5;              // 0..15
            int nc = (idx & 31) * 4;        // 0..124
            pb[q] = *(const float4*)(W + (long long)(k0 + kr) * Nc + n0 + nc);
        }
    };
    auto store_tiles = [&](int sbuf) {
#pragma unroll
        for (int q = 0; q < 2; q++) {
            int idx = t + q * 256;
            int row = idx >> 2;
            int kc  = (idx & 3) * 4;
            As[sbuf][kc + 0][row] = pa[q].x;
            As[sbuf][kc + 1][row] = pa[q].y;
            As[sbuf][kc + 2][row] = pa[q].z;
            As[sbuf][kc + 3][row] = pa[q].w;
            int kr = idx >> 5;
            int nc = (idx & 31) * 4;
            *(float4*)&Bs[sbuf][kr][nc] = pb[q];
        }
    };

    const int niter = K / BK;
    load_tiles(0);
    store_tiles(0);
    __syncthreads();
    int cur = 0;

    for (int it = 0; it < niter; it++) {
        if (it + 1 < niter) load_tiles((it + 1) * BK);

#pragma unroll
        for (int kk = 0; kk < BK; kk++) {
            float4 a0 = *(const float4*)&As[cur][kk][ty * 8];
            float4 a1 = *(const float4*)&As[cur][kk][ty * 8 + 4];
            float4 b0 = *(const float4*)&Bs[cur][kk][tx * 8];
            float4 b1 = *(const float4*)&Bs[cur][kk][tx * 8 + 4];
            unsigned long long bp[4];
            asm("mov.b64 %0, {%1,%2};" : "=l"(bp[0]) : "f"(b0.x), "f"(b0.y));
            asm("mov.b64 %0, {%1,%2};" : "=l"(bp[1]) : "f"(b0.z), "f"(b0.w));
            asm("mov.b64 %0, {%1,%2};" : "=l"(bp[2]) : "f"(b1.x), "f"(b1.y));
            asm("mov.b64 %0, {%1,%2};" : "=l"(bp[3]) : "f"(b1.z), "f"(b1.w));
            float av[8] = {a0.x, a0.y, a0.z, a0.w, a1.x, a1.y, a1.z, a1.w};
#pragma unroll
            for (int i = 0; i < 8; i++) {
                unsigned long long aa;
                asm("mov.b64 %0, {%1,%1};" : "=l"(aa) : "f"(av[i]));
#pragma unroll
                for (int jp = 0; jp < 4; jp++) {
                    asm("fma.rn.f32x2 %0, %1, %2, %0;"
                        : "+l"(acc[i][jp]) : "l"(aa), "l"(bp[jp]));
                }
            }
        }

        if (it + 1 < niter) {
            __syncthreads();
            store_tiles(cur ^ 1);
            cur ^= 1;
            __syncthreads();
        }
    }

    // --- epilogue: unpack + bias + activation + store (float4)
#pragma unroll
    for (int i = 0; i < 8; i++) {
        int grow = m0 + ty * 8 + i;
        if (grow >= M) continue;
        float c[8];
#pragma unroll
        for (int jp = 0; jp < 4; jp++) {
            asm("mov.b64 {%0,%1}, %2;"
                : "=f"(c[2 * jp]), "=f"(c[2 * jp + 1]) : "l"(acc[i][jp]));
        }
#pragma unroll
        for (int j = 0; j < 8; j += 4) {
            int gc = n0 + tx * 8 + j;
            float4 v;
            v.x = c[j + 0] + bias[gc + 0];
            v.y = c[j + 1] + bias[gc + 1];
            v.z = c[j + 2] + bias[gc + 2];
            v.w = c[j + 3] + bias[gc + 3];
            if (act == 1) {
                v.x = v.x > 0.f ? v.x : 0.01f * v.x;
                v.y = v.y > 0.f ? v.y : 0.01f * v.y;
                v.z = v.z > 0.f ? v.z : 0.01f * v.z;
                v.w = v.w > 0.f ? v.w : 0.01f * v.w;
            }
            *(float4*)(C + (long long)grow * Nc + gc) = v;
        }
    }
}

// ---------------- GRU elementwise update (float4) ----------------------------
__global__ void gru_kernel(float* __restrict__ doutp, int writeOut) {
    int idx = blockIdx.x * blockDim.x + threadIdx.x;   // over NN*32
    if (idx >= NN * 32) return;
    int n  = idx >> 5;
    int j4 = idx & 31;
    const float4* gi4 = (const float4*)(g_gi + (long long)n * 384);
    const float4* gh4 = (const float4*)(g_gh + (long long)n * 384);
    float4 ir  = gi4[j4],      hr = gh4[j4];
    float4 iz  = gi4[32 + j4], hz = gh4[32 + j4];
    float4 inn = gi4[64 + j4], hn = gh4[64 + j4];
    float4 h   = ((const float4*)(g_h + (long long)n * 128))[j4];
    float4 o;
    {
        float r = 1.f / (1.f + __expf(-(ir.x + hr.x)));
        float z = 1.f / (1.f + __expf(-(iz.x + hz.x)));
        float nv = tanhf(inn.x + r * hn.x);
        o.x = (1.f - z) * nv + z * h.x;
    }
    {
        float r = 1.f / (1.f + __expf(-(ir.y + hr.y)));
        float z = 1.f / (1.f + __expf(-(iz.y + hz.y)));
        float nv = tanhf(inn.y + r * hn.y);
        o.y = (1.f - z) * nv + z * h.y;
    }
    {
        float r = 1.f / (1.f + __expf(-(ir.z + hr.z)));
        float z = 1.f / (1.f + __expf(-(iz.z + hz.z)));
        float nv = tanhf(inn.z + r * hn.z);
        o.z = (1.f - z) * nv + z * h.z;
    }
    {
        float r = 1.f / (1.f + __expf(-(ir.w + hr.w)));
        float z = 1.f / (1.f + __expf(-(iz.w + hz.w)));
        float nv = tanhf(inn.w + r * hn.w);
        o.w = (1.f - z) * nv + z * h.w;
    }
    if (writeOut) ((float4*)doutp)[idx] = o;
    else          ((float4*)g_h)[idx]  = o;
}

// ---------------- launch -----------------------------------------------------
extern "C" void kernel_launch(void* const* d_in, const int* in_sizes, int n_in,
                              void* d_out, int out_size) {
    const float* x  = (const float*)d_in[0];
    const int*   ei = (const int*)d_in[1];     // int32 (JAX x64 disabled)
    const float* ea = (const float*)d_in[2];
    // d_in[3] = batch (unused)
    const float* W_embed = (const float*)d_in[4];
    const float* b_embed = (const float*)d_in[5];
    const float* W_snd   = (const float*)d_in[6];
    const float* b_snd   = (const float*)d_in[7];
    const float* W_rec   = (const float*)d_in[8];
    const float* b_rec   = (const float*)d_in[9];
    const float* W_ih    = (const float*)d_in[10];
    const float* b_ih    = (const float*)d_in[11];
    const float* W_hh    = (const float*)d_in[12];
    const float* b_hh    = (const float*)d_in[13];

    const int T = 256;
    const int rowBlocks = (NN + 127) / 128;   // 391

    // CSR build (per call, deterministic work)
    zero_cnt_kernel<<<(NN + T - 1) / T, T>>>();
    count_kernel<<<(EE + T - 1) / T, T>>>(ei);
    scan_kernel<<<1, 1024>>>();
    fill_kernel<<<(EE + T - 1) / T, T>>>(ei, ea);

    // embed: h = x @ W_embed + b_embed
    gemm_kernel<<<dim3(rowBlocks, 1), T>>>(x, -1, 64, -1, 0,
                                           W_embed, b_embed,
                                           nullptr, BUF_H, NN, 128, 0);

    for (int layer = 0; layer < 3; layer++) {
        // s = leaky_relu(h @ W_snd + b_snd)
        gemm_kernel<<<dim3(rowBlocks, 1), T>>>(nullptr, BUF_H, 128, -1, 0,
                                               W_snd, b_snd,
                                               nullptr, BUF_S, NN, 128, 1);
        // agg = segment_mean via CSR gather (no atomics)
        agg_kernel<<<(NN * 32 + T - 1) / T, T>>>();
        // m = leaky_relu([agg, h] @ W_rec + b_rec)
        gemm_kernel<<<dim3(rowBlocks, 2), T>>>(nullptr, BUF_AGG, 128, BUF_H, 128,
                                               W_rec, b_rec,
                                               nullptr, BUF_M, NN, 256, 1);
        // gi = m @ W_ih + b_ih ; gh = h @ W_hh + b_hh
        gemm_kernel<<<dim3(rowBlocks, 3), T>>>(nullptr, BUF_M, 256, -1, 0,
                                               W_ih, b_ih,
                                               nullptr, BUF_GI, NN, 384, 0);
        gemm_kernel<<<dim3(rowBlocks, 3), T>>>(nullptr, BUF_H, 128, -1, 0,
                                               W_hh, b_hh,
                                               nullptr, BUF_GH, NN, 384, 0);
        // GRU update (last layer writes d_out)
        gru_kernel<<<(NN * 32 + T - 1) / T, T>>>(
            (float*)d_out, layer == 2 ? 1 : 0);
    }
}

// round 10
// speedup vs baseline: 1.3774x; 1.0003x over previous
#include <cuda_runtime.h>
#include <cuda_bf16.h>

// Problem constants
#define NN 50000
#define EE 800000

// ---------------- scratch (device globals; no allocation allowed) -----------
__device__ float g_h  [(long long)NN * 128];
__device__ float g_s  [(long long)NN * 128];
__device__ float g_agg[(long long)NN * 128];
__device__ float g_m  [(long long)NN * 256];
__device__ float g_gi [(long long)NN * 384];
__device__ float g_gh [(long long)NN * 384];
__device__ float g_inv[NN];
__device__ int   g_cnt[NN];
__device__ int   g_start[NN + 1];
__device__ int   g_head[NN];
__device__ int   g_csr_row[EE];
__device__ float g_csr_ea[EE];

#define BUF_H   0
#define BUF_S   1
#define BUF_AGG 2
#define BUF_M   3
#define BUF_GI  4
#define BUF_GH  5

__device__ __forceinline__ float* buf(int id) {
    switch (id) {
        case BUF_H:   return g_h;
        case BUF_S:   return g_s;
        case BUF_AGG: return g_agg;
        case BUF_M:   return g_m;
        case BUF_GI:  return g_gi;
        case BUF_GH:  return g_gh;
    }
    return nullptr;
}

// ---------------- degree / CSR build ----------------------------------------
__global__ void zero_cnt_kernel() {
    int i = blockIdx.x * blockDim.x + threadIdx.x;
    if (i < NN) g_cnt[i] = 0;
}

// edge_index is int32 (JAX x64 disabled)
__global__ void count_kernel(const int* __restrict__ ei) {
    int e = blockIdx.x * blockDim.x + threadIdx.x;
    if (e < EE) {
        unsigned c = (unsigned)ei[EE + e];
        if (c < NN) atomicAdd(&g_cnt[c], 1);
    }
}

// Single-block exclusive scan over g_cnt -> g_start, g_head, g_inv.
__global__ void scan_kernel() {
    __shared__ int ssum[1024];
    const int CH = (NN + 1023) / 1024;   // 49
    int t = threadIdx.x;
    int beg = t * CH;
    int end = beg + CH; if (end > NN) end = NN;
    int s = 0;
    for (int i = beg; i < end; i++) s += g_cnt[i];
    ssum[t] = s;
    __syncthreads();
    for (int off = 1; off < 1024; off <<= 1) {
        int v = (t >= off) ? ssum[t - off] : 0;
        __syncthreads();
        ssum[t] += v;
        __syncthreads();
    }
    int run = ssum[t] - s;   // exclusive prefix for this chunk
    for (int i = beg; i < end; i++) {
        int c = g_cnt[i];
        g_start[i] = run;
        g_head[i]  = run;
        g_inv[i]   = 1.0f / (float)(c > 0 ? c : 1);
        run += c;
    }
    if (t == 1023) g_start[NN] = ssum[1023];
}

__global__ void fill_kernel(const int* __restrict__ ei,
                            const float* __restrict__ ea) {
    int e = blockIdx.x * blockDim.x + threadIdx.x;
    if (e >= EE) return;
    unsigned r = (unsigned)ei[e];
    unsigned c = (unsigned)ei[EE + e];
    if (c < NN) {
        int p = atomicAdd(&g_head[c], 1);
        g_csr_row[p] = (r < NN) ? (int)r : 0;
        g_csr_ea[p]  = ea[e];
    }
}

// ---------------- node-parallel aggregation (no atomics) --------------------
// One warp per node: agg[n] = (sum_{e in in(n)} s[row[e]] * ea[e]) * inv[n]
__global__ void agg_kernel() {
    int gid  = blockIdx.x * blockDim.x + threadIdx.x;
    int n    = gid >> 5;
    int lane = gid & 31;
    if (n >= NN) return;
    int beg = g_start[n];
    int end = g_start[n + 1];
    float4 acc = make_float4(0.f, 0.f, 0.f, 0.f);
    int e = beg;
    for (; e + 1 < end; e += 2) {
        int   r0 = g_csr_row[e];
        int   r1 = g_csr_row[e + 1];
        float a0 = g_csr_ea[e];
        float a1 = g_csr_ea[e + 1];
        float4 v0 = ((const float4*)(g_s + (long long)r0 * 128))[lane];
        float4 v1 = ((const float4*)(g_s + (long long)r1 * 128))[lane];
        acc.x += v0.x * a0 + v1.x * a1;
        acc.y += v0.y * a0 + v1.y * a1;
        acc.z += v0.z * a0 + v1.z * a1;
        acc.w += v0.w * a0 + v1.w * a1;
    }
    if (e < end) {
        int   r0 = g_csr_row[e];
        float a0 = g_csr_ea[e];
        float4 v0 = ((const float4*)(g_s + (long long)r0 * 128))[lane];
        acc.x += v0.x * a0; acc.y += v0.y * a0;
        acc.z += v0.z * a0; acc.w += v0.w * a0;
    }
    float iv = g_inv[n];
    acc.x *= iv; acc.y *= iv; acc.z *= iv; acc.w *= iv;
    ((float4*)(g_agg + (long long)n * 128))[lane] = acc;
}

// ---------------- SGEMM: double-buffered, packed f32x2 inner loop -----------
// C[M x Nc] = act( concat(A0, A1)[M x (K0+K1)] @ W[(K0+K1) x Nc] + bias )
// BM=BN=128, BK=16, 256 threads, 8x8 micro-tile per thread.
__global__ __launch_bounds__(256)
void gemm_kernel(const float* __restrict__ A0p, int A0id, int K0,
                 int A1id, int K1,
                 const float* __restrict__ W,
                 const float* __restrict__ bias,
                 float* __restrict__ Cp, int Cid,
                 int M, int Nc, int act) {
    const int BK = 16;
    __shared__ float As[2][BK][132];
    __shared__ float Bs[2][BK][132];

    const float* A0 = (A0id >= 0) ? buf(A0id) : A0p;
    const float* A1 = (A1id >= 0) ? buf(A1id) : nullptr;
    float*       C  = (Cid  >= 0) ? buf(Cid)  : Cp;

    const int K  = K0 + K1;
    const int m0 = blockIdx.x * 128;
    const int n0 = blockIdx.y * 128;
    const int t  = threadIdx.x;
    const int ty = t >> 4;          // 0..15
    const int tx = t & 15;          // 0..15

    // packed accumulators: acc[i][jp] holds (c[i][2jp], c[i][2jp+1])
    unsigned long long acc[8][4];
#pragma unroll
    for (int i = 0; i < 8; i++)
#pragma unroll
        for (int jp = 0; jp < 4; jp++) acc[i][jp] = 0ULL;

    float4 pa[2], pb[2];

    auto load_tiles = [&](int k0) {
#pragma unroll
        for (int q = 0; q < 2; q++) {
            int idx = t + q * 256;          // [0,512)
            int row = idx >> 2;             // 0..127
            int kc  = (idx & 3) * 4;        // 0,4,8,12
            int grow = m0 + row;
            float4 v = make_float4(0.f, 0.f, 0.f, 0.f);
            if (grow < M) {
                int kg = k0 + kc;
                if (kg < K0) v = *(const float4*)(A0 + (long long)grow * K0 + kg);
                else         v = *(const float4*)(A1 + (long long)grow * K1 + (kg - K0));
            }
            pa[q] = v;
            int kr = idx >> 5;              // 0..15
            int nc = (idx & 31) * 4;        // 0..124
            pb[q] = *(const float4*)(W + (long long)(k0 + kr) * Nc + n0 + nc);
        }
    };
    auto store_tiles = [&](int sbuf) {
#pragma unroll
        for (int q = 0; q < 2; q++) {
            int idx = t + q * 256;
            int row = idx >> 2;
            int kc  = (idx & 3) * 4;
            As[sbuf][kc + 0][row] = pa[q].x;
            As[sbuf][kc + 1][row] = pa[q].y;
            As[sbuf][kc + 2][row] = pa[q].z;
            As[sbuf][kc + 3][row] = pa[q].w;
            int kr = idx >> 5;
            int nc = (idx & 31) * 4;
            *(float4*)&Bs[sbuf][kr][nc] = pb[q];
        }
    };

    const int niter = K / BK;
    load_tiles(0);
    store_tiles(0);
    __syncthreads();
    int cur = 0;

    for (int it = 0; it < niter; it++) {
        if (it + 1 < niter) load_tiles((it + 1) * BK);

#pragma unroll
        for (int kk = 0; kk < BK; kk++) {
            float4 a0 = *(const float4*)&As[cur][kk][ty * 8];
            float4 a1 = *(const float4*)&As[cur][kk][ty * 8 + 4];
            float4 b0 = *(const float4*)&Bs[cur][kk][tx * 8];
            float4 b1 = *(const float4*)&Bs[cur][kk][tx * 8 + 4];
            unsigned long long bp[4];
            asm("mov.b64 %0, {%1,%2};" : "=l"(bp[0]) : "f"(b0.x), "f"(b0.y));
            asm("mov.b64 %0, {%1,%2};" : "=l"(bp[1]) : "f"(b0.z), "f"(b0.w));
            asm("mov.b64 %0, {%1,%2};" : "=l"(bp[2]) : "f"(b1.x), "f"(b1.y));
            asm("mov.b64 %0, {%1,%2};" : "=l"(bp[3]) : "f"(b1.z), "f"(b1.w));
            float av[8] = {a0.x, a0.y, a0.z, a0.w, a1.x, a1.y, a1.z, a1.w};
#pragma unroll
            for (int i = 0; i < 8; i++) {
                unsigned long long aa;
                asm("mov.b64 %0, {%1,%1};" : "=l"(aa) : "f"(av[i]));
#pragma unroll
                for (int jp = 0; jp < 4; jp++) {
                    asm("fma.rn.f32x2 %0, %1, %2, %0;"
                        : "+l"(acc[i][jp]) : "l"(aa), "l"(bp[jp]));
                }
            }
        }

        if (it + 1 < niter) {
            __syncthreads();
            store_tiles(cur ^ 1);
            cur ^= 1;
            __syncthreads();
        }
    }

    // --- epilogue: unpack + bias + activation + store (float4)
#pragma unroll
    for (int i = 0; i < 8; i++) {
        int grow = m0 + ty * 8 + i;
        if (grow >= M) continue;
        float c[8];
#pragma unroll
        for (int jp = 0; jp < 4; jp++) {
            asm("mov.b64 {%0,%1}, %2;"
                : "=f"(c[2 * jp]), "=f"(c[2 * jp + 1]) : "l"(acc[i][jp]));
        }
#pragma unroll
        for (int j = 0; j < 8; j += 4) {
            int gc = n0 + tx * 8 + j;
            float4 v;
            v.x = c[j + 0] + bias[gc + 0];
            v.y = c[j + 1] + bias[gc + 1];
            v.z = c[j + 2] + bias[gc + 2];
            v.w = c[j + 3] + bias[gc + 3];
            if (act == 1) {
                v.x = v.x > 0.f ? v.x : 0.01f * v.x;
                v.y = v.y > 0.f ? v.y : 0.01f * v.y;
                v.z = v.z > 0.f ? v.z : 0.01f * v.z;
                v.w = v.w > 0.f ? v.w : 0.01f * v.w;
            }
            *(float4*)(C + (long long)grow * Nc + gc) = v;
        }
    }
}

// ---------------- GRU elementwise update (float4) ----------------------------
__global__ void gru_kernel(float* __restrict__ doutp, int writeOut) {
    int idx = blockIdx.x * blockDim.x + threadIdx.x;   // over NN*32
    if (idx >= NN * 32) return;
    int n  = idx >> 5;
    int j4 = idx & 31;
    const float4* gi4 = (const float4*)(g_gi + (long long)n * 384);
    const float4* gh4 = (const float4*)(g_gh + (long long)n * 384);
    float4 ir  = gi4[j4],      hr = gh4[j4];
    float4 iz  = gi4[32 + j4], hz = gh4[32 + j4];
    float4 inn = gi4[64 + j4], hn = gh4[64 + j4];
    float4 h   = ((const float4*)(g_h + (long long)n * 128))[j4];
    float4 o;
    {
        float r = 1.f / (1.f + __expf(-(ir.x + hr.x)));
        float z = 1.f / (1.f + __expf(-(iz.x + hz.x)));
        float nv = tanhf(inn.x + r * hn.x);
        o.x = (1.f - z) * nv + z * h.x;
    }
    {
        float r = 1.f / (1.f + __expf(-(ir.y + hr.y)));
        float z = 1.f / (1.f + __expf(-(iz.y + hz.y)));
        float nv = tanhf(inn.y + r * hn.y);
        o.y = (1.f - z) * nv + z * h.y;
    }
    {
        float r = 1.f / (1.f + __expf(-(ir.z + hr.z)));
        float z = 1.f / (1.f + __expf(-(iz.z + hz.z)));
        float nv = tanhf(inn.z + r * hn.z);
        o.z = (1.f - z) * nv + z * h.z;
    }
    {
        float r = 1.f / (1.f + __expf(-(ir.w + hr.w)));
        float z = 1.f / (1.f + __expf(-(iz.w + hz.w)));
        float nv = tanhf(inn.w + r * hn.w);
        o.w = (1.f - z) * nv + z * h.w;
    }
    if (writeOut) ((float4*)doutp)[idx] = o;
    else          ((float4*)g_h)[idx]  = o;
}

// ---------------- launch -----------------------------------------------------
extern "C" void kernel_launch(void* const* d_in, const int* in_sizes, int n_in,
                              void* d_out, int out_size) {
    const float* x  = (const float*)d_in[0];
    const int*   ei = (const int*)d_in[1];     // int32 (JAX x64 disabled)
    const float* ea = (const float*)d_in[2];
    // d_in[3] = batch (unused)
    const float* W_embed = (const float*)d_in[4];
    const float* b_embed = (const float*)d_in[5];
    const float* W_snd   = (const float*)d_in[6];
    const float* b_snd   = (const float*)d_in[7];
    const float* W_rec   = (const float*)d_in[8];
    const float* b_rec   = (const float*)d_in[9];
    const float* W_ih    = (const float*)d_in[10];
    const float* b_ih    = (const float*)d_in[11];
    const float* W_hh    = (const float*)d_in[12];
    const float* b_hh    = (const float*)d_in[13];

    const int T = 256;
    const int rowBlocks = (NN + 127) / 128;   // 391

    // CSR build (per call, deterministic work)
    zero_cnt_kernel<<<(NN + T - 1) / T, T>>>();
    count_kernel<<<(EE + T - 1) / T, T>>>(ei);
    scan_kernel<<<1, 1024>>>();
    fill_kernel<<<(EE + T - 1) / T, T>>>(ei, ea);

    // embed: h = x @ W_embed + b_embed
    gemm_kernel<<<dim3(rowBlocks, 1), T>>>(x, -1, 64, -1, 0,
                                           W_embed, b_embed,
                                           nullptr, BUF_H, NN, 128, 0);

    for (int layer = 0; layer < 3; layer++) {
        // s = leaky_relu(h @ W_snd + b_snd)
        gemm_kernel<<<dim3(rowBlocks, 1), T>>>(nullptr, BUF_H, 128, -1, 0,
                                               W_snd, b_snd,
                                               nullptr, BUF_S, NN, 128, 1);
        // agg = segment_mean via CSR gather (no atomics)
        agg_kernel<<<(NN * 32 + T - 1) / T, T>>>();
        // m = leaky_relu([agg, h] @ W_rec + b_rec)
        gemm_kernel<<<dim3(rowBlocks, 2), T>>>(nullptr, BUF_AGG, 128, BUF_H, 128,
                                               W_rec, b_rec,
                                               nullptr, BUF_M, NN, 256, 1);
        // gi = m @ W_ih + b_ih ; gh = h @ W_hh + b_hh
        gemm_kernel<<<dim3(rowBlocks, 3), T>>>(nullptr, BUF_M, 256, -1, 0,
                                               W_ih, b_ih,
                                               nullptr, BUF_GI, NN, 384, 0);
        gemm_kernel<<<dim3(rowBlocks, 3), T>>>(nullptr, BUF_H, 128, -1, 0,
                                               W_hh, b_hh,
                                               nullptr, BUF_GH, NN, 384, 0);
        // GRU update (last layer writes d_out)
        gru_kernel<<<(NN * 32 + T - 1) / T, T>>>(
            (float*)d_out, layer == 2 ? 1 : 0);
    }
}